// round 7
// baseline (speedup 1.0000x reference)
#include <cuda_runtime.h>
#include <cstdint>

#define TPB   128     // 4 warps; each warp = 16 pixels; block = 64 pixels
#define XP    72      // exchange-buffer pitch (mod 32 == 8 -> conflict-free)

__device__ __forceinline__ uint32_t to_tf32(float f) {
    uint32_t r; asm("cvt.rna.tf32.f32 %0, %1;" : "=r"(r) : "f"(f)); return r;
}
__device__ __forceinline__ void mma8(float& c0, float& c1, float& c2, float& c3,
                                     uint32_t a0, uint32_t a1, uint32_t a2, uint32_t a3,
                                     uint32_t b0, uint32_t b1) {
    asm volatile("mma.sync.aligned.m16n8k8.row.col.f32.tf32.tf32.f32 "
                 "{%0,%1,%2,%3},{%4,%5,%6,%7},{%8,%9},{%0,%1,%2,%3};"
                 : "+f"(c0), "+f"(c1), "+f"(c2), "+f"(c3)
                 : "r"(a0), "r"(a1), "r"(a2), "r"(a3), "r"(b0), "r"(b1));
}
__device__ __forceinline__ int wslot(int c) {   // pack (w[8s+tg], w[8s+tg+4]) adjacent
    return ((c >> 3) << 3) + ((c & 3) << 1) + ((c >> 2) & 1);
}

// smem word layout: exchange + weights + biases (~41 KB total, fits default 48KB)
#define OFF_XB   0                          // [32][XP] MLP exchange (tf32)
#define OFF_WKV  (32 * XP)                  // [64][72] rows 0-31 key, 32-63 value
#define OFF_WQ   (OFF_WKV + 64 * 72)        // [32][72]
#define OFF_WD1  (OFF_WQ  + 32 * 72)        // [16][40]
#define OFF_WD2  (OFF_WD1 + 16 * 40)        // [8][24]
#define OFF_WD3  (OFF_WD2 + 8 * 24)         // [16][8]
#define OFF_BIA  (OFF_WD3 + 16 * 8)         // float[113]
#define SMEM_WORDS (OFF_BIA + 113)

__global__ __launch_bounds__(TPB, 4)
void fused_tc3_kernel(const float* __restrict__ kv_in, const float* __restrict__ q_in,
                      const float* __restrict__ key_w,   const float* __restrict__ key_b,
                      const float* __restrict__ value_w, const float* __restrict__ value_b,
                      const float* __restrict__ query_w, const float* __restrict__ query_b,
                      const float* __restrict__ scale,
                      const float* __restrict__ d1_w, const float* __restrict__ d2_w,
                      const float* __restrict__ d3_w, const float* __restrict__ d3_b,
                      float* __restrict__ out)
{
    __shared__ uint32_t sm[SMEM_WORDS];
    uint32_t* xb   = sm + OFF_XB;
    uint32_t* wKVp = sm + OFF_WKV;
    uint32_t* wQp  = sm + OFF_WQ;
    uint32_t* wD1p = sm + OFF_WD1;
    uint32_t* wD2p = sm + OFF_WD2;
    uint32_t* wD3p = sm + OFF_WD3;
    float*    bia  = (float*)(sm + OFF_BIA);

    const int tid = threadIdx.x;

    // ---- weights -> smem (tf32, pair-packed) ----
    for (int i = tid; i < 2048; i += TPB) {
        int o = i >> 6, s = wslot(i & 63);
        wKVp[o * 72 + s]        = to_tf32(key_w[i]);
        wKVp[(o + 32) * 72 + s] = to_tf32(value_w[i]);
        wQp[o * 72 + s]         = to_tf32(query_w[i]);
    }
    for (int i = tid; i < 512; i += TPB) wD1p[(i >> 5) * 40 + wslot(i & 31)] = to_tf32(d1_w[i]);
    if (tid < 128) wD2p[(tid >> 4) * 24 + wslot(tid & 15)] = to_tf32(d2_w[tid]);
    if (tid < 128) wD3p[(tid >> 3) * 8  + wslot(tid & 7) ] = to_tf32(d3_w[tid]);
    if (tid < 32) { bia[tid] = key_b[tid]; bia[32 + tid] = value_b[tid]; bia[64 + tid] = query_b[tid]; }
    if (tid >= 32 && tid < 48) bia[96 + tid - 32] = d3_b[tid - 32];
    if (tid == 48) bia[112] = scale[0];
    __syncthreads();

    const int warp = tid >> 5, lane = tid & 31;
    const int g = lane >> 2, tg = lane & 3;
    const int col0 = warp * 16 + g;          // this thread's pixel column within block

    const int pg0 = blockIdx.x << 6;         // 64 pixels per block (never crosses batch)
    const int bb  = pg0 >> 16;
    const int px0 = pg0 & 65535;

    // per-thread pixel base pointers
    const float* kvp = kv_in + ((size_t)bb << 22) + px0 + col0;
    const float* qpp = q_in  + ((size_t)bb << 22) + px0 + col0;

    // C fragments: [0..3]=k, [4..7]=v, [8..11]=q (bias folded into init)
    float C[12][4];
    #pragma unroll
    for (int j = 0; j < 8; j++) {
        float b0 = bia[8 * j + 2 * tg], b1 = bia[8 * j + 2 * tg + 1];
        C[j][0] = b0; C[j][1] = b1; C[j][2] = b0; C[j][3] = b1;
    }
    #pragma unroll
    for (int j = 0; j < 4; j++) {
        float b0 = bia[64 + 8 * j + 2 * tg], b1 = bia[64 + 8 * j + 2 * tg + 1];
        C[8 + j][0] = b0; C[8 + j][1] = b1; C[8 + j][2] = b0; C[8 + j][3] = b1;
    }

    // ---- conv GEMMs: A-fragments straight from GMEM, depth-2 prefetch ----
    float fa[2][8];
    #pragma unroll
    for (int s = 0; s < 2; s++) {
        size_t c0 = (size_t)(8 * s + tg) << 16;
        size_t c1 = (size_t)(8 * s + tg + 4) << 16;
        fa[s][0] = __ldg(kvp + c0);  fa[s][1] = __ldg(kvp + c0 + 8);
        fa[s][2] = __ldg(kvp + c1);  fa[s][3] = __ldg(kvp + c1 + 8);
        fa[s][4] = __ldg(qpp + c0);  fa[s][5] = __ldg(qpp + c0 + 8);
        fa[s][6] = __ldg(qpp + c1);  fa[s][7] = __ldg(qpp + c1 + 8);
    }
    #pragma unroll
    for (int s = 0; s < 8; s++) {
        const int kb = 8 * s;
        uint32_t a0 = to_tf32(fa[s & 1][0]), a1 = to_tf32(fa[s & 1][1]);
        uint32_t a2 = to_tf32(fa[s & 1][2]), a3 = to_tf32(fa[s & 1][3]);
        uint32_t q0 = to_tf32(fa[s & 1][4]), q1 = to_tf32(fa[s & 1][5]);
        uint32_t q2 = to_tf32(fa[s & 1][6]), q3 = to_tf32(fa[s & 1][7]);
        if (s < 6) {  // prefetch step s+2
            size_t c0 = (size_t)(8 * (s + 2) + tg) << 16;
            size_t c1 = (size_t)(8 * (s + 2) + tg + 4) << 16;
            fa[s & 1][0] = __ldg(kvp + c0);  fa[s & 1][1] = __ldg(kvp + c0 + 8);
            fa[s & 1][2] = __ldg(kvp + c1);  fa[s & 1][3] = __ldg(kvp + c1 + 8);
            fa[s & 1][4] = __ldg(qpp + c0);  fa[s & 1][5] = __ldg(qpp + c0 + 8);
            fa[s & 1][6] = __ldg(qpp + c1);  fa[s & 1][7] = __ldg(qpp + c1 + 8);
        }
        #pragma unroll
        for (int j = 0; j < 8; j++) {
            uint2 b = *(const uint2*)&wKVp[(8 * j + g) * 72 + kb + 2 * tg];
            mma8(C[j][0], C[j][1], C[j][2], C[j][3], a0, a1, a2, a3, b.x, b.y);
        }
        #pragma unroll
        for (int j = 0; j < 4; j++) {
            uint2 b = *(const uint2*)&wQp[(8 * j + g) * 72 + kb + 2 * tg];
            mma8(C[8 + j][0], C[8 + j][1], C[8 + j][2], C[8 + j][3], q0, q1, q2, q3, b.x, b.y);
        }
    }

    // ---- gating: x = sigmoid(k*q*scale) * v -> warp-private exchange columns ----
    const float sc = bia[112];
    __syncwarp();
    #pragma unroll
    for (int j = 0; j < 4; j++) {
        #pragma unroll
        for (int e = 0; e < 4; e++) {
            float t = C[j][e] * C[8 + j][e] * sc;
            float sg = 1.0f / (1.0f + __expf(-t));
            float x = sg * C[4 + j][e];
            int c = 8 * j + 2 * tg + (e & 1);
            int p = warp * 16 + g + ((e >> 1) << 3);
            xb[c * XP + p] = to_tf32(x);
        }
    }
    __syncwarp();

    // ---- d1: 32 -> 16 (relu) ----
    float D1[2][4] = {};
    #pragma unroll
    for (int s = 0; s < 4; s++) {
        const int kb = 8 * s;
        uint32_t a0 = xb[(kb + tg    ) * XP + col0    ];
        uint32_t a1 = xb[(kb + tg    ) * XP + col0 + 8];
        uint32_t a2 = xb[(kb + tg + 4) * XP + col0    ];
        uint32_t a3 = xb[(kb + tg + 4) * XP + col0 + 8];
        #pragma unroll
        for (int j = 0; j < 2; j++) {
            uint2 b = *(const uint2*)&wD1p[(8 * j + g) * 40 + kb + 2 * tg];
            mma8(D1[j][0], D1[j][1], D1[j][2], D1[j][3], a0, a1, a2, a3, b.x, b.y);
        }
    }
    __syncwarp();
    #pragma unroll
    for (int j = 0; j < 2; j++)
        #pragma unroll
        for (int e = 0; e < 4; e++) {
            int c = 8 * j + 2 * tg + (e & 1);
            int p = warp * 16 + g + ((e >> 1) << 3);
            xb[c * XP + p] = to_tf32(fmaxf(D1[j][e], 0.0f));
        }
    __syncwarp();

    // ---- d2: 16 -> 8 (relu) ----
    float D2[4] = {};
    #pragma unroll
    for (int s = 0; s < 2; s++) {
        const int kb = 8 * s;
        uint32_t a0 = xb[(kb + tg    ) * XP + col0    ];
        uint32_t a1 = xb[(kb + tg    ) * XP + col0 + 8];
        uint32_t a2 = xb[(kb + tg + 4) * XP + col0    ];
        uint32_t a3 = xb[(kb + tg + 4) * XP + col0 + 8];
        uint2 b = *(const uint2*)&wD2p[g * 24 + kb + 2 * tg];
        mma8(D2[0], D2[1], D2[2], D2[3], a0, a1, a2, a3, b.x, b.y);
    }
    __syncwarp();
    #pragma unroll
    for (int e = 0; e < 4; e++) {
        int c = 2 * tg + (e & 1);
        int p = warp * 16 + g + ((e >> 1) << 3);
        xb[c * XP + p] = to_tf32(fmaxf(D2[e], 0.0f));
    }
    __syncwarp();

    // ---- d3: 8 -> 16 (+bias) ----
    float D3[2][4];
    #pragma unroll
    for (int j = 0; j < 2; j++) {
        float b0 = bia[96 + 8 * j + 2 * tg], b1 = bia[96 + 8 * j + 2 * tg + 1];
        D3[j][0] = b0; D3[j][1] = b1; D3[j][2] = b0; D3[j][3] = b1;
    }
    {
        uint32_t a0 = xb[(tg    ) * XP + col0    ];
        uint32_t a1 = xb[(tg    ) * XP + col0 + 8];
        uint32_t a2 = xb[(tg + 4) * XP + col0    ];
        uint32_t a3 = xb[(tg + 4) * XP + col0 + 8];
        #pragma unroll
        for (int j = 0; j < 2; j++) {
            uint2 b = *(const uint2*)&wD3p[(8 * j + g) * 8 + 2 * tg];
            mma8(D3[j][0], D3[j][1], D3[j][2], D3[j][3], a0, a1, a2, a3, b.x, b.y);
        }
    }

    // ---- store ----
    const int pixg = px0 + warp * 16 + g;
    #pragma unroll
    for (int j = 0; j < 2; j++)
        #pragma unroll
        for (int e = 0; e < 4; e++) {
            int ch = 8 * j + 2 * tg + (e & 1);
            int pp = pixg + ((e >> 1) << 3);
            out[(((size_t)(bb * 16 + ch)) << 16) + pp] = D3[j][e];
        }
}

extern "C" void kernel_launch(void* const* d_in, const int* in_sizes, int n_in,
                              void* d_out, int out_size)
{
    const float* kv_in   = (const float*)d_in[0];
    const float* q_in    = (const float*)d_in[1];
    const float* key_w   = (const float*)d_in[2];
    const float* key_b   = (const float*)d_in[3];
    const float* value_w = (const float*)d_in[4];
    const float* value_b = (const float*)d_in[5];
    const float* query_w = (const float*)d_in[6];
    const float* query_b = (const float*)d_in[7];
    const float* scale   = (const float*)d_in[8];
    const float* d1_w    = (const float*)d_in[9];
    const float* d2_w    = (const float*)d_in[10];
    const float* d3_w    = (const float*)d_in[11];
    const float* d3_b    = (const float*)d_in[12];
    float* out = (float*)d_out;

    fused_tc3_kernel<<<16384, TPB>>>(kv_in, q_in, key_w, key_b, value_w, value_b,
                                     query_w, query_b, scale, d1_w, d2_w, d3_w, d3_b,
                                     out);
}

// round 10
// speedup vs baseline: 1.8212x; 1.8212x over previous
#include <cuda_runtime.h>
#include <cstdint>

#define TPB     256
#define PITCH   136      // activation pitch (words); 136 % 32 == 8 -> conflict-free A loads
#define NGRP    8192     // 8192 groups of 128 pixels
#define GRID    296      // 2 persistent CTAs per SM (148 SMs)

__device__ __forceinline__ uint32_t to_tf32(float f) {
    uint32_t r; asm("cvt.rna.tf32.f32 %0, %1;" : "=r"(r) : "f"(f)); return r;
}
__device__ __forceinline__ void mma8(float& c0, float& c1, float& c2, float& c3,
                                     uint32_t a0, uint32_t a1, uint32_t a2, uint32_t a3,
                                     uint32_t b0, uint32_t b1) {
    asm volatile("mma.sync.aligned.m16n8k8.row.col.f32.tf32.tf32.f32 "
                 "{%0,%1,%2,%3},{%4,%5,%6,%7},{%8,%9},{%0,%1,%2,%3};"
                 : "+f"(c0), "+f"(c1), "+f"(c2), "+f"(c3)
                 : "r"(a0), "r"(a1), "r"(a2), "r"(a3), "r"(b0), "r"(b1));
}

// smem word layout
#define OFF_KV   0                        // [64][PITCH] kv activations (tf32)
#define OFF_Q    (64 * PITCH)             // [64][PITCH] q activations / MLP exchange
#define OFF_WKV  (2 * 64 * PITCH)         // [8 ksteps][32 lanes][20] b-pair cells (k j0-3, v j4-7)
#define OFF_WQ   (OFF_WKV + 8*32*20)      // [8][32][12] (q j0-3)
#define OFF_WD1  (OFF_WQ  + 8*32*12)      // [4][32][4]
#define OFF_WD2  (OFF_WD1 + 4*32*4)       // [2][32][2]
#define OFF_WD3  (OFF_WD2 + 2*32*2)       // [32][4]
#define OFF_BIA  (OFF_WD3 + 32*4)         // float[113]
#define SMEM_WORDS (OFF_BIA + 113)

__global__ __launch_bounds__(TPB, 2)
void fused_tc4_kernel(const float* __restrict__ kv_in, const float* __restrict__ q_in,
                      const float* __restrict__ key_w,   const float* __restrict__ key_b,
                      const float* __restrict__ value_w, const float* __restrict__ value_b,
                      const float* __restrict__ query_w, const float* __restrict__ query_b,
                      const float* __restrict__ scale,
                      const float* __restrict__ d1_w, const float* __restrict__ d2_w,
                      const float* __restrict__ d3_w, const float* __restrict__ d3_b,
                      float* __restrict__ out)
{
    extern __shared__ uint32_t sm[];
    uint32_t* smKV = sm + OFF_KV;
    uint32_t* smQ  = sm + OFF_Q;
    uint32_t* wKV2 = sm + OFF_WKV;
    uint32_t* wQ2  = sm + OFF_WQ;
    uint32_t* wD1  = sm + OFF_WD1;
    uint32_t* wD2  = sm + OFF_WD2;
    uint32_t* wD3  = sm + OFF_WD3;
    float*    bia  = (float*)(sm + OFF_BIA);

    const int tid = threadIdx.x;

    // ---- one-time weight staging: B-fragment-major, LDS.128-ready ----
    // cell index for conv: (s*32 + 4g+tg)*pitch + 2j + off   (off: 0 = col tg, 1 = col tg+4)
    for (int i = tid; i < 2048; i += TPB) {
        int o = i >> 6, c = i & 63;
        int j = o >> 3, g = o & 7;
        int s = c >> 3, t4 = c & 7;
        int tg = t4 & 3, off = t4 >> 2;
        int cell = s * 32 + 4 * g + tg;
        wKV2[cell * 20 + 2 * j       + off] = to_tf32(key_w[i]);
        wKV2[cell * 20 + 2 * (j + 4) + off] = to_tf32(value_w[i]);
        wQ2 [cell * 12 + 2 * j       + off] = to_tf32(query_w[i]);
    }
    for (int i = tid; i < 512; i += TPB) {       // d1 [16][32]
        int o = i >> 5, c = i & 31;
        int j = o >> 3, g = o & 7;
        int s = c >> 3, t4 = c & 7;
        wD1[(s * 32 + 4 * g + (t4 & 3)) * 4 + 2 * j + (t4 >> 2)] = to_tf32(d1_w[i]);
    }
    if (tid < 128) {                              // d2 [8][16]
        int g = tid >> 4, c = tid & 15;
        int s = c >> 3, t4 = c & 7;
        wD2[(s * 32 + 4 * g + (t4 & 3)) * 2 + (t4 >> 2)] = to_tf32(d2_w[tid]);
    }
    if (tid < 128) {                              // d3 [16][8]
        int o = tid >> 3, t4 = tid & 7;
        int j = o >> 3, g = o & 7;
        wD3[(4 * g + (t4 & 3)) * 4 + 2 * j + (t4 >> 2)] = to_tf32(d3_w[tid]);
    }
    if (tid < 32) { bia[tid] = key_b[tid]; bia[32 + tid] = value_b[tid]; bia[64 + tid] = query_b[tid]; }
    if (tid >= 32 && tid < 48) bia[96 + tid - 32] = d3_b[tid - 32];
    if (tid == 48) bia[112] = scale[0];
    __syncthreads();

    const int warp = tid >> 5, lane = tid & 31;
    const int g = lane >> 2, tg = lane & 3;
    const int col0 = warp * 16 + g;

    const float scv = bia[112];
    float bC[12][2], bD3[2][2];
    #pragma unroll
    for (int j = 0; j < 8; j++)  { bC[j][0] = bia[8*j + 2*tg];      bC[j][1] = bia[8*j + 2*tg + 1]; }
    #pragma unroll
    for (int j = 0; j < 4; j++)  { bC[8+j][0] = bia[64 + 8*j + 2*tg]; bC[8+j][1] = bia[64 + 8*j + 2*tg + 1]; }
    #pragma unroll
    for (int j = 0; j < 2; j++)  { bD3[j][0] = bia[96 + 8*j + 2*tg]; bD3[j][1] = bia[96 + 8*j + 2*tg + 1]; }

    // ---- persistent loop over pixel groups ----
    for (int grp = blockIdx.x; grp < NGRP; grp += GRID) {
        const int pg0 = grp << 7;
        const int bb  = pg0 >> 16;
        const int px0 = pg0 & 65535;
        const float* kvb = kv_in + ((size_t)bb << 22) + px0;
        const float* qpb = q_in  + ((size_t)bb << 22) + px0;

        __syncthreads();   // previous group's exchange reads done before overwrite

        for (int i = tid; i < 2048; i += TPB) {
            int c = i >> 5, p = i & 31;
            float4 a = *(const float4*)(kvb + ((size_t)c << 16) + 4 * p);
            float4 b = *(const float4*)(qpb + ((size_t)c << 16) + 4 * p);
            uint4 ua = make_uint4(to_tf32(a.x), to_tf32(a.y), to_tf32(a.z), to_tf32(a.w));
            uint4 ub = make_uint4(to_tf32(b.x), to_tf32(b.y), to_tf32(b.z), to_tf32(b.w));
            *(uint4*)&smKV[c * PITCH + 4 * p] = ua;
            *(uint4*)&smQ [c * PITCH + 4 * p] = ub;
        }
        __syncthreads();

        // C fragments: [0..3]=k, [4..7]=v, [8..11]=q
        float C[12][4];
        #pragma unroll
        for (int j = 0; j < 12; j++) {
            C[j][0] = bC[j][0]; C[j][1] = bC[j][1]; C[j][2] = bC[j][0]; C[j][3] = bC[j][1];
        }

        #pragma unroll
        for (int s = 0; s < 8; s++) {
            const int kb = 8 * s;
            uint32_t a0 = smKV[(kb + tg    ) * PITCH + col0    ];
            uint32_t a1 = smKV[(kb + tg    ) * PITCH + col0 + 8];
            uint32_t a2 = smKV[(kb + tg + 4) * PITCH + col0    ];
            uint32_t a3 = smKV[(kb + tg + 4) * PITCH + col0 + 8];
            const uint32_t* wb = wKV2 + (s * 32 + lane) * 20;
            #pragma unroll
            for (int jj = 0; jj < 4; jj++) {
                uint4 B = *(const uint4*)(wb + 4 * jj);     // b-pairs for j=2jj, 2jj+1
                mma8(C[2*jj  ][0], C[2*jj  ][1], C[2*jj  ][2], C[2*jj  ][3], a0, a1, a2, a3, B.x, B.y);
                mma8(C[2*jj+1][0], C[2*jj+1][1], C[2*jj+1][2], C[2*jj+1][3], a0, a1, a2, a3, B.z, B.w);
            }
            uint32_t q0 = smQ[(kb + tg    ) * PITCH + col0    ];
            uint32_t q1 = smQ[(kb + tg    ) * PITCH + col0 + 8];
            uint32_t q2 = smQ[(kb + tg + 4) * PITCH + col0    ];
            uint32_t q3 = smQ[(kb + tg + 4) * PITCH + col0 + 8];
            const uint32_t* wq = wQ2 + (s * 32 + lane) * 12;
            #pragma unroll
            for (int jj = 0; jj < 2; jj++) {
                uint4 B = *(const uint4*)(wq + 4 * jj);
                mma8(C[8+2*jj  ][0], C[8+2*jj  ][1], C[8+2*jj  ][2], C[8+2*jj  ][3], q0, q1, q2, q3, B.x, B.y);
                mma8(C[8+2*jj+1][0], C[8+2*jj+1][1], C[8+2*jj+1][2], C[8+2*jj+1][3], q0, q1, q2, q3, B.z, B.w);
            }
        }

        // ---- gating -> warp-private exchange columns (reuse smQ) ----
        uint32_t* xb = smQ;
        __syncwarp();
        #pragma unroll
        for (int j = 0; j < 4; j++) {
            #pragma unroll
            for (int e = 0; e < 4; e++) {
                float t = C[j][e] * C[8 + j][e] * scv;
                float sg = 1.0f / (1.0f + __expf(-t));
                float x = sg * C[4 + j][e];
                int c = 8 * j + 2 * tg + (e & 1);
                int p = warp * 16 + g + ((e >> 1) << 3);
                xb[c * PITCH + p] = to_tf32(x);
            }
        }
        __syncwarp();

        // ---- d1: 32 -> 16 (relu) ----
        float D1[2][4] = {};
        #pragma unroll
        for (int s = 0; s < 4; s++) {
            const int kb = 8 * s;
            uint32_t a0 = xb[(kb + tg    ) * PITCH + col0    ];
            uint32_t a1 = xb[(kb + tg    ) * PITCH + col0 + 8];
            uint32_t a2 = xb[(kb + tg + 4) * PITCH + col0    ];
            uint32_t a3 = xb[(kb + tg + 4) * PITCH + col0 + 8];
            uint4 B = *(const uint4*)(wD1 + (s * 32 + lane) * 4);
            mma8(D1[0][0], D1[0][1], D1[0][2], D1[0][3], a0, a1, a2, a3, B.x, B.y);
            mma8(D1[1][0], D1[1][1], D1[1][2], D1[1][3], a0, a1, a2, a3, B.z, B.w);
        }
        __syncwarp();
        #pragma unroll
        for (int j = 0; j < 2; j++)
            #pragma unroll
            for (int e = 0; e < 4; e++) {
                int c = 8 * j + 2 * tg + (e & 1);
                int p = warp * 16 + g + ((e >> 1) << 3);
                xb[c * PITCH + p] = to_tf32(fmaxf(D1[j][e], 0.0f));
            }
        __syncwarp();

        // ---- d2: 16 -> 8 (relu) ----
        float D2[4] = {};
        #pragma unroll
        for (int s = 0; s < 2; s++) {
            const int kb = 8 * s;
            uint32_t a0 = xb[(kb + tg    ) * PITCH + col0    ];
            uint32_t a1 = xb[(kb + tg    ) * PITCH + col0 + 8];
            uint32_t a2 = xb[(kb + tg + 4) * PITCH + col0    ];
            uint32_t a3 = xb[(kb + tg + 4) * PITCH + col0 + 8];
            uint2 B = *(const uint2*)(wD2 + (s * 32 + lane) * 2);
            mma8(D2[0], D2[1], D2[2], D2[3], a0, a1, a2, a3, B.x, B.y);
        }
        __syncwarp();
        #pragma unroll
        for (int e = 0; e < 4; e++) {
            int c = 2 * tg + (e & 1);
            int p = warp * 16 + g + ((e >> 1) << 3);
            xb[c * PITCH + p] = to_tf32(fmaxf(D2[e], 0.0f));
        }
        __syncwarp();

        // ---- d3: 8 -> 16 (+bias) ----
        float D3[2][4];
        #pragma unroll
        for (int j = 0; j < 2; j++) {
            D3[j][0] = bD3[j][0]; D3[j][1] = bD3[j][1]; D3[j][2] = bD3[j][0]; D3[j][3] = bD3[j][1];
        }
        {
            uint32_t a0 = xb[(tg    ) * PITCH + col0    ];
            uint32_t a1 = xb[(tg    ) * PITCH + col0 + 8];
            uint32_t a2 = xb[(tg + 4) * PITCH + col0    ];
            uint32_t a3 = xb[(tg + 4) * PITCH + col0 + 8];
            uint4 B = *(const uint4*)(wD3 + lane * 4);
            mma8(D3[0][0], D3[0][1], D3[0][2], D3[0][3], a0, a1, a2, a3, B.x, B.y);
            mma8(D3[1][0], D3[1][1], D3[1][2], D3[1][3], a0, a1, a2, a3, B.z, B.w);
        }

        // ---- store ----
        const int pixg = px0 + warp * 16 + g;
        #pragma unroll
        for (int j = 0; j < 2; j++)
            #pragma unroll
            for (int e = 0; e < 4; e++) {
                int ch = 8 * j + 2 * tg + (e & 1);
                int pp = pixg + ((e >> 1) << 3);
                out[(((size_t)(bb * 16 + ch)) << 16) + pp] = D3[j][e];
            }
    }
}

extern "C" void kernel_launch(void* const* d_in, const int* in_sizes, int n_in,
                              void* d_out, int out_size)
{
    const float* kv_in   = (const float*)d_in[0];
    const float* q_in    = (const float*)d_in[1];
    const float* key_w   = (const float*)d_in[2];
    const float* key_b   = (const float*)d_in[3];
    const float* value_w = (const float*)d_in[4];
    const float* value_b = (const float*)d_in[5];
    const float* query_w = (const float*)d_in[6];
    const float* query_b = (const float*)d_in[7];
    const float* scale   = (const float*)d_in[8];
    const float* d1_w    = (const float*)d_in[9];
    const float* d2_w    = (const float*)d_in[10];
    const float* d3_w    = (const float*)d_in[11];
    const float* d3_b    = (const float*)d_in[12];
    float* out = (float*)d_out;

    const int SMEM = SMEM_WORDS * 4;   // ~105.9 KB
    static int configured = 0;
    if (!configured) {
        cudaFuncSetAttribute(fused_tc4_kernel, cudaFuncAttributeMaxDynamicSharedMemorySize, SMEM);
        configured = 1;
    }

    fused_tc4_kernel<<<GRID, TPB, SMEM>>>(kv_in, q_in, key_w, key_b, value_w, value_b,
                                          query_w, query_b, scale, d1_w, d2_w, d3_w, d3_b,
                                          out);
}